// round 3
// baseline (speedup 1.0000x reference)
#include <cuda_runtime.h>
#include <cuda_fp16.h>
#include <stdint.h>

#define D      1024
#define NROWS  65536

#define BM 128
#define BN 128
#define BK 32
#define LDK 40   // BK + 8 halves pad -> 80B row stride, conflict-free & 16B aligned

// ---------------- scratch (static device globals; no allocations) -------------
__device__ __half g_xh[(size_t)NROWS * D];   // fp16 copy of inputs
__device__ __half g_gh[(size_t)NROWS * D];   // fp16 activated hidden
__device__ float  g_S [D * D];               // fp32 accumulator for M = U - I
__device__ __half g_Pa[D * D];               // ping power buffer (scaled (10A)^k)
__device__ __half g_Pb[D * D];               // pong power buffer
__device__ __half g_Bneg[D * D];             // -10A  (== (10A)^T, skew-symmetric)
__device__ __half g_M1[D * D];               // fp16 M1
__device__ __half g_M2[D * D];               // fp16 M2
__device__ float  g_part[2 * D];             // row partial sums for means
__device__ float  g_pass[1];                 // passthrough scalar

__device__ __forceinline__ uint32_t smem_u32(const void* p) {
    return (uint32_t)__cvta_generic_to_shared(p);
}

// ---------------- small helper kernels ----------------------------------------

__global__ void convert_x_kernel(const float* __restrict__ x, __half* __restrict__ xh) {
    size_t i = ((size_t)blockIdx.x * blockDim.x + threadIdx.x) * 4;
    float4 v = *(const float4*)(x + i);
    *(__half2*)(xh + i)     = __floats2half2_rn(v.x, v.y);
    *(__half2*)(xh + i + 2) = __floats2half2_rn(v.z, v.w);
}

// A = 0.5(W - W^T); S = 2A; Pa = h(10A); Bneg = h(-10A)
__global__ void skew_kernel(const float* __restrict__ W,
                            float* __restrict__ S,
                            __half* __restrict__ P1,
                            __half* __restrict__ Bneg) {
    int idx = blockIdx.x * blockDim.x + threadIdx.x;
    int i = idx >> 10, j = idx & (D - 1);
    float a = 0.5f * (W[idx] - W[j * D + i]);
    S[idx]    = 2.0f * a;
    P1[idx]   = __float2half(10.0f * a);
    Bneg[idx] = __float2half(-10.0f * a);
}

__global__ void finalize_kernel(const float* __restrict__ S, __half* __restrict__ Mh) {
    int idx = blockIdx.x * blockDim.x + threadIdx.x;
    Mh[idx] = __float2half(S[idx]);
}

// Deterministic passthrough: blocks 0..1023 sum u1 rows, 1024..2047 sum u2 rows.
__global__ void row_sum_kernel(const float* __restrict__ u1,
                               const float* __restrict__ u2,
                               float* __restrict__ part) {
    int b = blockIdx.x;
    const float* src = (b < D) ? (u1 + (size_t)b * D) : (u2 + (size_t)(b - D) * D);
    __shared__ float sm[256];
    float s = 0.f;
    for (int j = threadIdx.x; j < D; j += 256) s += src[j];
    sm[threadIdx.x] = s;
    __syncthreads();
    for (int o = 128; o > 0; o >>= 1) {
        if (threadIdx.x < o) sm[threadIdx.x] += sm[threadIdx.x + o];
        __syncthreads();
    }
    if (threadIdx.x == 0) part[b] = sm[0];
}

__global__ void pass_kernel(const float* __restrict__ part,
                            const float* __restrict__ theta,
                            float* __restrict__ out) {
    __shared__ float sm[1024];
    sm[threadIdx.x] = part[threadIdx.x] + part[threadIdx.x + 1024];
    __syncthreads();
    for (int o = 512; o > 0; o >>= 1) {
        if (threadIdx.x < o) sm[threadIdx.x] += sm[threadIdx.x + o];
        __syncthreads();
    }
    if (threadIdx.x == 0)
        out[0] = (sm[0] / 1048576.0f + theta[0]) * 1e-6f;
}

// ---------------- fused fp16 GEMM:  C = Aop[M,K] @ Bop[N,K]^T -------------------
// Epilogues:
//   EPI_SMALL : Ph = half(C);  Sacc += coeff * C
//   EPI_L1    : h = C + float(ident);  rotate pairs by theta;  Gout = half(h)
//   EPI_L2    : Out = C + float(ident) + passv
#define EPI_SMALL 0
#define EPI_L1    1
#define EPI_L2    2

template <int EPI>
__global__ void __launch_bounds__(256)
gemm_kernel(const __half* __restrict__ Aop,
            const __half* __restrict__ Bop,
            int Kdim,
            float coeff,
            float* __restrict__ Sacc,
            __half* __restrict__ Ph,
            const __half* __restrict__ ident,
            const float* __restrict__ theta,
            __half* __restrict__ Gout,
            const float* __restrict__ passv,
            float* __restrict__ Out)
{
    __shared__ __half As[2][BM][LDK];
    __shared__ __half Bs[2][BN][LDK];

    const int tid  = threadIdx.x;
    const int warp = tid >> 5, lane = tid & 31;
    const int wr = warp >> 2, wc = warp & 3;        // 2 x 4 warp grid
    const int grp = lane >> 2, q = lane & 3;

    const size_t rowBase = (size_t)blockIdx.y * BM;
    const int    colBase = blockIdx.x * BN;

    float acc[4][4][4];
    #pragma unroll
    for (int a = 0; a < 4; a++)
        #pragma unroll
        for (int b = 0; b < 4; b++)
            #pragma unroll
            for (int c = 0; c < 4; c++) acc[a][b][c] = 0.f;

    auto load_tile = [&](int kt, int buf) {
        const int k0 = kt * BK;
        #pragma unroll
        for (int i = 0; i < 2; i++) {
            int c = tid + i * 256;
            int r = c >> 2, cc = (c & 3) * 8;       // 16B chunk
            const __half* gA = Aop + (rowBase + r) * (size_t)Kdim + k0 + cc;
            uint32_t sA = smem_u32(&As[buf][r][cc]);
            asm volatile("cp.async.cg.shared.global [%0], [%1], 16;\n" :: "r"(sA), "l"(gA));
            const __half* gB = Bop + (size_t)(colBase + r) * Kdim + k0 + cc;
            uint32_t sB = smem_u32(&Bs[buf][r][cc]);
            asm volatile("cp.async.cg.shared.global [%0], [%1], 16;\n" :: "r"(sB), "l"(gB));
        }
    };

    const int ktiles = Kdim / BK;
    load_tile(0, 0);
    asm volatile("cp.async.commit_group;\n");
    asm volatile("cp.async.wait_group 0;\n");
    __syncthreads();

    int buf = 0;
    for (int kt = 0; kt < ktiles; kt++) {
        if (kt + 1 < ktiles) {
            load_tile(kt + 1, buf ^ 1);
            asm volatile("cp.async.commit_group;\n");
        }
        #pragma unroll
        for (int kp = 0; kp < 2; kp++) {
            const int kk = kp * 16 + q * 2;
            uint32_t af[4][4];
            #pragma unroll
            for (int mi = 0; mi < 4; mi++) {
                int r = wr * 64 + mi * 16 + grp;
                af[mi][0] = *(const uint32_t*)&As[buf][r][kk];
                af[mi][1] = *(const uint32_t*)&As[buf][r + 8][kk];
                af[mi][2] = *(const uint32_t*)&As[buf][r][kk + 8];
                af[mi][3] = *(const uint32_t*)&As[buf][r + 8][kk + 8];
            }
            uint32_t bf[4][2];
            #pragma unroll
            for (int ni = 0; ni < 4; ni++) {
                int n = wc * 32 + ni * 8 + grp;
                bf[ni][0] = *(const uint32_t*)&Bs[buf][n][kk];
                bf[ni][1] = *(const uint32_t*)&Bs[buf][n][kk + 8];
            }
            #pragma unroll
            for (int mi = 0; mi < 4; mi++)
                #pragma unroll
                for (int ni = 0; ni < 4; ni++) {
                    asm volatile(
                        "mma.sync.aligned.m16n8k16.row.col.f32.f16.f16.f32 "
                        "{%0,%1,%2,%3}, {%4,%5,%6,%7}, {%8,%9}, {%0,%1,%2,%3};\n"
                        : "+f"(acc[mi][ni][0]), "+f"(acc[mi][ni][1]),
                          "+f"(acc[mi][ni][2]), "+f"(acc[mi][ni][3])
                        : "r"(af[mi][0]), "r"(af[mi][1]), "r"(af[mi][2]), "r"(af[mi][3]),
                          "r"(bf[ni][0]), "r"(bf[ni][1]));
                }
        }
        if (kt + 1 < ktiles) {
            asm volatile("cp.async.wait_group 0;\n");
        }
        __syncthreads();
        buf ^= 1;
    }

    // ---------------- epilogue ----------------
    float cs = 0.f, sn = 0.f, pv = 0.f;
    if (EPI == EPI_L1) { float th = theta[0]; cs = cosf(th); sn = sinf(th); }
    if (EPI == EPI_L2) { pv = passv[0]; }

    #pragma unroll
    for (int mi = 0; mi < 4; mi++) {
        const int rloc = wr * 64 + mi * 16 + grp;
        #pragma unroll
        for (int rr = 0; rr < 2; rr++) {
            const size_t grow = rowBase + rloc + rr * 8;
            #pragma unroll
            for (int ni = 0; ni < 4; ni++) {
                const int gcol = colBase + wc * 32 + ni * 8 + q * 2;  // even
                float v0 = acc[mi][ni][rr * 2 + 0];
                float v1 = acc[mi][ni][rr * 2 + 1];
                const size_t idx = grow * D + gcol;    // output N == D everywhere
                if (EPI == EPI_SMALL) {
                    float2 sv = *(float2*)&Sacc[idx];
                    sv.x += coeff * v0;
                    sv.y += coeff * v1;
                    *(float2*)&Sacc[idx] = sv;
                    *(__half2*)&Ph[idx] = __floats2half2_rn(v0, v1);
                } else if (EPI == EPI_L1) {
                    __half2 id = *(const __half2*)&ident[idx];
                    float h0 = v0 + __low2float(id);
                    float h1 = v1 + __high2float(id);
                    float g0 = cs * h0 - sn * h1;
                    float g1 = sn * h0 + cs * h1;
                    *(__half2*)&Gout[idx] = __floats2half2_rn(g0, g1);
                } else {
                    __half2 id = *(const __half2*)&ident[idx];
                    float2 o;
                    o.x = v0 + __low2float(id) + pv;
                    o.y = v1 + __high2float(id) + pv;
                    *(float2*)&Out[idx] = o;
                }
            }
        }
    }
}

// ---------------- host launcher ------------------------------------------------

extern "C" void kernel_launch(void* const* d_in, const int* in_sizes, int n_in,
                              void* d_out, int out_size) {
    const float* x     = (const float*)d_in[0];
    const float* u1    = (const float*)d_in[1];
    const float* u2    = (const float*)d_in[2];
    const float* theta = (const float*)d_in[3];
    float* out = (float*)d_out;

    __half *xh, *gh, *Pa, *Pb, *Bneg, *M1, *M2;
    float *S, *part, *pass;
    cudaGetSymbolAddress((void**)&xh,   g_xh);
    cudaGetSymbolAddress((void**)&gh,   g_gh);
    cudaGetSymbolAddress((void**)&Pa,   g_Pa);
    cudaGetSymbolAddress((void**)&Pb,   g_Pb);
    cudaGetSymbolAddress((void**)&Bneg, g_Bneg);
    cudaGetSymbolAddress((void**)&M1,   g_M1);
    cudaGetSymbolAddress((void**)&M2,   g_M2);
    cudaGetSymbolAddress((void**)&S,    g_S);
    cudaGetSymbolAddress((void**)&part, g_part);
    cudaGetSymbolAddress((void**)&pass, g_pass);

    // passthrough scalar (deterministic 2-stage reduction)
    row_sum_kernel<<<2 * D, 256>>>(u1, u2, part);
    pass_kernel<<<1, 1024>>>(part, theta, pass);

    // fp16 copy of inputs
    convert_x_kernel<<<(int)(((size_t)NROWS * D) / 4 / 256), 256>>>(x, xh);

    const dim3 gsmall(D / BN, D / BM);       // 8 x 8
    const dim3 gbig(D / BN, NROWS / BM);     // 8 x 512

    // ---- M1 = 2(A + A^2 + ... + A^5) + A^6, built from scaled powers (10A)^k ----
    skew_kernel<<<D * D / 256, 256>>>(u1, S, Pa, Bneg);
    gemm_kernel<EPI_SMALL><<<gsmall, 256>>>(Pa, Bneg, D, 2e-2f, S, Pb, nullptr, nullptr, nullptr, nullptr, nullptr);
    gemm_kernel<EPI_SMALL><<<gsmall, 256>>>(Pb, Bneg, D, 2e-3f, S, Pa, nullptr, nullptr, nullptr, nullptr, nullptr);
    gemm_kernel<EPI_SMALL><<<gsmall, 256>>>(Pa, Bneg, D, 2e-4f, S, Pb, nullptr, nullptr, nullptr, nullptr, nullptr);
    gemm_kernel<EPI_SMALL><<<gsmall, 256>>>(Pb, Bneg, D, 2e-5f, S, Pa, nullptr, nullptr, nullptr, nullptr, nullptr);
    gemm_kernel<EPI_SMALL><<<gsmall, 256>>>(Pa, Bneg, D, 1e-6f, S, Pb, nullptr, nullptr, nullptr, nullptr, nullptr);
    finalize_kernel<<<D * D / 256, 256>>>(S, M1);

    // layer 1: g = rotate(x + x @ M1^T, theta)   (identity added from fp16 x)
    gemm_kernel<EPI_L1><<<gbig, 256>>>(xh, M1, D, 0.f, nullptr, nullptr, xh, theta, gh, nullptr, nullptr);

    // ---- M2 ----
    skew_kernel<<<D * D / 256, 256>>>(u2, S, Pa, Bneg);
    gemm_kernel<EPI_SMALL><<<gsmall, 256>>>(Pa, Bneg, D, 2e-2f, S, Pb, nullptr, nullptr, nullptr, nullptr, nullptr);
    gemm_kernel<EPI_SMALL><<<gsmall, 256>>>(Pb, Bneg, D, 2e-3f, S, Pa, nullptr, nullptr, nullptr, nullptr, nullptr);
    gemm_kernel<EPI_SMALL><<<gsmall, 256>>>(Pa, Bneg, D, 2e-4f, S, Pb, nullptr, nullptr, nullptr, nullptr, nullptr);
    gemm_kernel<EPI_SMALL><<<gsmall, 256>>>(Pb, Bneg, D, 2e-5f, S, Pa, nullptr, nullptr, nullptr, nullptr, nullptr);
    gemm_kernel<EPI_SMALL><<<gsmall, 256>>>(Pa, Bneg, D, 1e-6f, S, Pb, nullptr, nullptr, nullptr, nullptr, nullptr);
    finalize_kernel<<<D * D / 256, 256>>>(S, M2);

    // layer 2: out = g + g @ M2^T + passthrough
    gemm_kernel<EPI_L2><<<gbig, 256>>>(gh, M2, D, 0.f, nullptr, nullptr, gh, nullptr, nullptr, pass, out);
}

// round 5
// speedup vs baseline: 1.5011x; 1.5011x over previous
#include <cuda_runtime.h>
#include <cuda_fp16.h>
#include <stdint.h>

#define D      1024
#define NROWS  65536
#define DD     (D * D)

// GEMM tile: 128x128, BK=64, 3-stage cp.async, ldmatrix + XOR swizzle
#define TBK     64
#define KT      (D / TBK)        // 16
#define STAGEB  32768            // (128 rows A + 128 rows B) * 64 halves * 2B
#define SMEMSZ  (3 * STAGEB + 1024)

// ---------------- scratch (static device globals; no allocations) -------------
__device__ __half g_xh[(size_t)NROWS * D];   // fp16 inputs
__device__ __half g_gh[(size_t)NROWS * D];   // fp16 activated hidden
__device__ float  g_S [2 * DD];              // fp32 accumulators (both layers)
__device__ __half g_Pa[2 * DD];              // ping power buffers (scaled (10A)^k)
__device__ __half g_Pb[2 * DD];              // pong power buffers
__device__ __half g_Bneg[2 * DD];            // -10A  (== (10A)^T)
__device__ __half g_M [2 * DD];              // fp16 M1 | M2
__device__ float  g_part[2 * D];
__device__ float  g_pass[1];

__device__ __forceinline__ uint32_t smem_u32(const void* p) {
    return (uint32_t)__cvta_generic_to_shared(p);
}

#define LDSM_X4(r0, r1, r2, r3, addr) \
    asm volatile("ldmatrix.sync.aligned.m8n8.x4.shared.b16 {%0,%1,%2,%3}, [%4];" \
                 : "=r"(r0), "=r"(r1), "=r"(r2), "=r"(r3) : "r"(addr))

// ---------------- small helper kernels ----------------------------------------

__global__ void convert_x_kernel(const float* __restrict__ x, __half* __restrict__ xh) {
    size_t i = ((size_t)blockIdx.x * blockDim.x + threadIdx.x) * 4;
    float4 v = *(const float4*)(x + i);
    *(__half2*)(xh + i)     = __floats2half2_rn(v.x, v.y);
    *(__half2*)(xh + i + 2) = __floats2half2_rn(v.z, v.w);
}

// batched z in {0,1}: A = 0.5(W - W^T); S = 2A; Pa = h(10A); Bneg = h(-10A)
__global__ void skew_kernel(const float* __restrict__ W1, const float* __restrict__ W2,
                            float* __restrict__ S, __half* __restrict__ P1,
                            __half* __restrict__ Bneg) {
    int gidx = blockIdx.x * blockDim.x + threadIdx.x;
    int z = gidx >> 20;
    int idx = gidx & (DD - 1);
    const float* W = z ? W2 : W1;
    int i = idx >> 10, j = idx & (D - 1);
    float a = 0.5f * (W[idx] - W[j * D + i]);
    S[gidx]    = 2.0f * a;
    P1[gidx]   = __float2half(10.0f * a);
    Bneg[gidx] = __float2half(-10.0f * a);
}

__global__ void row_sum_kernel(const float* __restrict__ u1,
                               const float* __restrict__ u2,
                               float* __restrict__ part) {
    int b = blockIdx.x;
    const float* src = (b < D) ? (u1 + (size_t)b * D) : (u2 + (size_t)(b - D) * D);
    __shared__ float sm[256];
    float s = 0.f;
    for (int j = threadIdx.x; j < D; j += 256) s += src[j];
    sm[threadIdx.x] = s;
    __syncthreads();
    for (int o = 128; o > 0; o >>= 1) {
        if (threadIdx.x < o) sm[threadIdx.x] += sm[threadIdx.x + o];
        __syncthreads();
    }
    if (threadIdx.x == 0) part[b] = sm[0];
}

__global__ void pass_kernel(const float* __restrict__ part,
                            const float* __restrict__ theta,
                            float* __restrict__ out) {
    __shared__ float sm[1024];
    sm[threadIdx.x] = part[threadIdx.x] + part[threadIdx.x + 1024];
    __syncthreads();
    for (int o = 512; o > 0; o >>= 1) {
        if (threadIdx.x < o) sm[threadIdx.x] += sm[threadIdx.x + o];
        __syncthreads();
    }
    if (threadIdx.x == 0)
        out[0] = (sm[0] / 1048576.0f + theta[0]) * 1e-6f;
}

// ---------------- unified HMMA GEMM: C = A[M,K] @ B[N,K]^T  (K = D) -------------
// EPI 0 (SMALL): Ph = half(C);  Sacc += coeff*C            (Neumann chain step)
// EPI 3 (FINAL): Ph = half(Sacc + coeff*C)                 (fused finalize -> M)
// EPI 1 (L1)   : h = C + ident; rotate pairs by theta; Ph = half(h)
// EPI 2 (L2)   : OutF = C + ident + passv
template <int EPI>
__global__ void __launch_bounds__(256, 2)
gemm_ldsm(const __half* __restrict__ Aop, const __half* __restrict__ Bop,
          float coeff, float* __restrict__ Sacc, __half* __restrict__ Ph,
          const __half* __restrict__ ident, const float* __restrict__ theta,
          const float* __restrict__ passv, float* __restrict__ OutF)
{
    extern __shared__ char dsm_raw[];
    char* dsm = (char*)(((uintptr_t)dsm_raw + 1023) & ~(uintptr_t)1023);
    const uint32_t sbase = smem_u32(dsm);

    const int tid  = threadIdx.x;
    const int w    = tid >> 5, lane = tid & 31;
    const int wr = w >> 2, wc = w & 3;            // 2 x 4 warp grid -> 64x32 per warp
    const int grp = lane >> 2, q = lane & 3;
    const int lrow = lane & 15, lk = lane >> 4;   // ldmatrix lane decomposition

    const size_t zoff    = (size_t)blockIdx.z * DD;   // chain batching (0 for big)
    const size_t rowBase = (size_t)blockIdx.y * 128;
    const int    colBase = blockIdx.x * 128;
    const __half* A = Aop + zoff;
    const __half* B = Bop + zoff;

    float acc[4][4][4];
    #pragma unroll
    for (int a = 0; a < 4; a++)
        #pragma unroll
        for (int b = 0; b < 4; b++)
            #pragma unroll
            for (int c = 0; c < 4; c++) acc[a][b][c] = 0.f;

    auto load_tile = [&](int kt) {
        const int stage = kt % 3;
        const int k0 = kt * TBK;
        #pragma unroll
        for (int i = 0; i < 8; i++) {
            int id  = tid + (i << 8);              // 0..2047 16B chunks
            int isB = id >> 10;
            int rc  = id & 1023;
            int row = rc >> 3, c = rc & 7;
            uint32_t sw = ((uint32_t)row << 7) | (((uint32_t)(c ^ (row & 7))) << 4);
            const __half* g = (isB ? (B + (size_t)(colBase + row) * D)
                                   : (A + (rowBase + row) * (size_t)D)) + k0 + (c << 3);
            uint32_t s = sbase + stage * STAGEB + (isB << 14) + sw;
            asm volatile("cp.async.cg.shared.global [%0], [%1], 16;\n" :: "r"(s), "l"(g));
        }
        asm volatile("cp.async.commit_group;\n");
    };

    load_tile(0);
    load_tile(1);

    for (int kt = 0; kt < KT; kt++) {
        if (kt == KT - 1) asm volatile("cp.async.wait_group 0;\n");
        else              asm volatile("cp.async.wait_group 1;\n");
        __syncthreads();

        const uint32_t aS = sbase + (kt % 3) * STAGEB;
        const uint32_t bS = aS + 16384;

        #pragma unroll
        for (int kp = 0; kp < 4; kp++) {
            const uint32_t ch = (uint32_t)(kp * 2 + lk);
            uint32_t a[4][4];
            #pragma unroll
            for (int mi = 0; mi < 4; mi++) {
                int row = wr * 64 + mi * 16 + lrow;
                uint32_t ad = aS + ((uint32_t)row << 7) + ((ch ^ (uint32_t)(row & 7)) << 4);
                LDSM_X4(a[mi][0], a[mi][1], a[mi][2], a[mi][3], ad);
            }
            uint32_t b[4][2];
            #pragma unroll
            for (int np = 0; np < 2; np++) {
                int row = wc * 32 + np * 16 + lrow;
                uint32_t bd = bS + ((uint32_t)row << 7) + ((ch ^ (uint32_t)(row & 7)) << 4);
                uint32_t r0, r1, r2, r3;
                LDSM_X4(r0, r1, r2, r3, bd);
                b[np * 2 + 0][0] = r0; b[np * 2 + 1][0] = r1;
                b[np * 2 + 0][1] = r2; b[np * 2 + 1][1] = r3;
            }
            #pragma unroll
            for (int mi = 0; mi < 4; mi++)
                #pragma unroll
                for (int ni = 0; ni < 4; ni++) {
                    asm volatile(
                        "mma.sync.aligned.m16n8k16.row.col.f32.f16.f16.f32 "
                        "{%0,%1,%2,%3}, {%4,%5,%6,%7}, {%8,%9}, {%0,%1,%2,%3};\n"
                        : "+f"(acc[mi][ni][0]), "+f"(acc[mi][ni][1]),
                          "+f"(acc[mi][ni][2]), "+f"(acc[mi][ni][3])
                        : "r"(a[mi][0]), "r"(a[mi][1]), "r"(a[mi][2]), "r"(a[mi][3]),
                          "r"(b[ni][0]), "r"(b[ni][1]));
                }
        }
        if (kt + 2 < KT) load_tile(kt + 2);
    }

    // ---------------- epilogue ----------------
    float cs = 0.f, sn = 0.f, pv = 0.f;
    if (EPI == 1) { float th = theta[0]; cs = cosf(th); sn = sinf(th); }
    if (EPI == 2) { pv = passv[0]; }
    float* S  = (EPI == 0 || EPI == 3) ? (Sacc + zoff) : nullptr;
    __half* P = (EPI != 2) ? (Ph + zoff) : nullptr;

    #pragma unroll
    for (int mi = 0; mi < 4; mi++) {
        const int rloc = wr * 64 + mi * 16 + grp;
        #pragma unroll
        for (int rr = 0; rr < 2; rr++) {
            const size_t grow = rowBase + rloc + rr * 8;
            #pragma unroll
            for (int ni = 0; ni < 4; ni++) {
                const int gcol = colBase + wc * 32 + ni * 8 + q * 2;
                float v0 = acc[mi][ni][rr * 2 + 0];
                float v1 = acc[mi][ni][rr * 2 + 1];
                const size_t idx = grow * D + gcol;
                if (EPI == 0) {
                    float2 sv = *(float2*)&S[idx];
                    sv.x += coeff * v0;
                    sv.y += coeff * v1;
                    *(float2*)&S[idx] = sv;
                    *(__half2*)&P[idx] = __floats2half2_rn(v0, v1);
                } else if (EPI == 3) {
                    float2 sv = *(float2*)&S[idx];
                    *(__half2*)&P[idx] = __floats2half2_rn(sv.x + coeff * v0,
                                                           sv.y + coeff * v1);
                } else if (EPI == 1) {
                    __half2 id = *(const __half2*)&ident[idx];
                    float h0 = v0 + __low2float(id);
                    float h1 = v1 + __high2float(id);
                    *(__half2*)&P[idx] = __floats2half2_rn(cs * h0 - sn * h1,
                                                           sn * h0 + cs * h1);
                } else {
                    __half2 id = *(const __half2*)&ident[idx];
                    float2 o;
                    o.x = v0 + __low2float(id) + pv;
                    o.y = v1 + __high2float(id) + pv;
                    *(float2*)&OutF[idx] = o;
                }
            }
        }
    }
}

// ---------------- host launcher ------------------------------------------------

extern "C" void kernel_launch(void* const* d_in, const int* in_sizes, int n_in,
                              void* d_out, int out_size) {
    const float* x     = (const float*)d_in[0];
    const float* u1    = (const float*)d_in[1];
    const float* u2    = (const float*)d_in[2];
    const float* theta = (const float*)d_in[3];
    float* out = (float*)d_out;

    __half *xh, *gh, *Pa, *Pb, *Bneg, *M;
    float *S, *part, *pass;
    cudaGetSymbolAddress((void**)&xh,   g_xh);
    cudaGetSymbolAddress((void**)&gh,   g_gh);
    cudaGetSymbolAddress((void**)&Pa,   g_Pa);
    cudaGetSymbolAddress((void**)&Pb,   g_Pb);
    cudaGetSymbolAddress((void**)&Bneg, g_Bneg);
    cudaGetSymbolAddress((void**)&M,    g_M);
    cudaGetSymbolAddress((void**)&S,    g_S);
    cudaGetSymbolAddress((void**)&part, g_part);
    cudaGetSymbolAddress((void**)&pass, g_pass);

    cudaFuncSetAttribute(gemm_ldsm<0>, cudaFuncAttributeMaxDynamicSharedMemorySize, SMEMSZ);
    cudaFuncSetAttribute(gemm_ldsm<1>, cudaFuncAttributeMaxDynamicSharedMemorySize, SMEMSZ);
    cudaFuncSetAttribute(gemm_ldsm<2>, cudaFuncAttributeMaxDynamicSharedMemorySize, SMEMSZ);
    cudaFuncSetAttribute(gemm_ldsm<3>, cudaFuncAttributeMaxDynamicSharedMemorySize, SMEMSZ);

    // passthrough scalar
    row_sum_kernel<<<2 * D, 256>>>(u1, u2, part);
    pass_kernel<<<1, 1024>>>(part, theta, pass);

    // fp16 inputs
    convert_x_kernel<<<(int)(((size_t)NROWS * D) / 4 / 256), 256>>>(x, xh);

    // Neumann chains for BOTH layers, batched over blockIdx.z
    skew_kernel<<<2 * DD / 256, 256>>>(u1, u2, S, Pa, Bneg);
    const dim3 gsm(8, 8, 2);
    gemm_ldsm<0><<<gsm, 256, SMEMSZ>>>(Pa, Bneg, 2e-2f, S, Pb, nullptr, nullptr, nullptr, nullptr);
    gemm_ldsm<0><<<gsm, 256, SMEMSZ>>>(Pb, Bneg, 2e-3f, S, Pa, nullptr, nullptr, nullptr, nullptr);
    gemm_ldsm<0><<<gsm, 256, SMEMSZ>>>(Pa, Bneg, 2e-4f, S, Pb, nullptr, nullptr, nullptr, nullptr);
    gemm_ldsm<0><<<gsm, 256, SMEMSZ>>>(Pb, Bneg, 2e-5f, S, Pa, nullptr, nullptr, nullptr, nullptr);
    gemm_ldsm<3><<<gsm, 256, SMEMSZ>>>(Pa, Bneg, 1e-6f, S, M,  nullptr, nullptr, nullptr, nullptr);

    // layer 1: g = rotate(x + x @ M1^T, theta)
    const dim3 gbig(8, NROWS / 128);
    gemm_ldsm<1><<<gbig, 256, SMEMSZ>>>(xh, M, 0.f, nullptr, gh, xh, theta, nullptr, nullptr);
    // layer 2: out = g + g @ M2^T + passthrough
    gemm_ldsm<2><<<gbig, 256, SMEMSZ>>>(gh, M + DD, 0.f, nullptr, nullptr, gh, nullptr, pass, out);
}